// round 12
// baseline (speedup 1.0000x reference)
#include <cuda_runtime.h>
#include <cuda_fp16.h>
#include <mma.h>

using namespace nvcuda;

#define N_NODES 50000
#define N_EDGES 1600000
// h layout: [N, 128] (4 heads x 32)

typedef unsigned long long ull;

// Scratch (device globals — no allocation allowed)
__device__ __half g_h[(size_t)N_NODES * 128];   // projected features fp16 [N,128]
__device__ int    g_rowptr[N_NODES + 1];        // CSR offsets over sorted dst
__device__ __half g_Wh[128 * 128];              // W in fp16, row-major [k][c]

// ---------------------------------------------------------------------------
// Packed f32x2 helpers. Packs of DISTINCT values (mov.b64 {lo,hi}) are
// register-allocation-only (free); only dup-packs cost a MOV.
// ---------------------------------------------------------------------------
__device__ __forceinline__ ull fma2(ull a, ull b, ull c) {
    ull d;
    asm("fma.rn.f32x2 %0, %1, %2, %3;" : "=l"(d) : "l"(a), "l"(b), "l"(c));
    return d;
}
__device__ __forceinline__ ull mul2(ull a, ull b) {
    ull d;
    asm("mul.rn.f32x2 %0, %1, %2;" : "=l"(d) : "l"(a), "l"(b));
    return d;
}
__device__ __forceinline__ ull add2(ull a, ull b) {
    ull d;
    asm("add.rn.f32x2 %0, %1, %2;" : "=l"(d) : "l"(a), "l"(b));
    return d;
}
__device__ __forceinline__ ull dup2(float x) {
    ull r;
    asm("mov.b64 %0, {%1, %1};" : "=l"(r) : "f"(x));
    return r;
}
__device__ __forceinline__ float2 unpack2(ull u) {
    float2 f;
    asm("mov.b64 {%0, %1}, %2;" : "=f"(f.x), "=f"(f.y) : "l"(u));
    return f;
}
// half2 (as u32) -> packed f32x2: 2x F2F, pack is allocation-only
__device__ __forceinline__ ull h2f2(unsigned int h) {
    ull r;
    asm("{\n\t"
        ".reg .b16 lo, hi;\n\t"
        ".reg .f32 f0, f1;\n\t"
        "mov.b32 {lo, hi}, %1;\n\t"
        "cvt.f32.f16 f0, lo;\n\t"
        "cvt.f32.f16 f1, hi;\n\t"
        "mov.b64 %0, {f0, f1};\n\t"
        "}" : "=l"(r) : "r"(h));
    return r;
}
__device__ __forceinline__ ull shfl_xor64(ull v, int m) {
    unsigned lo = (unsigned)v, hi = (unsigned)(v >> 32);
    lo = __shfl_xor_sync(0xffffffffu, lo, m);
    hi = __shfl_xor_sync(0xffffffffu, hi, m);
    return ((ull)hi << 32) | (ull)lo;
}

// ---------------------------------------------------------------------------
// Kernel 0: W -> fp16 (one-time, 16384 elements)
// ---------------------------------------------------------------------------
__global__ void wh_kernel(const float* __restrict__ W) {
    const int i = blockIdx.x * 256 + threadIdx.x;
    if (i < 128 * 128) g_Wh[i] = __float2half(__ldg(&W[i]));
}

// ---------------------------------------------------------------------------
// Kernel 1: h = feat @ W via wmma (HMMA, fp16 in / fp32 accum / fp16 out).
// Tensor pipe was 0% while we fought for the FFMA pipe — move the GEMM there.
// Block = 256 thr (8 warps), 32 nodes/block. sA = feat tile fp16 (8KB),
// sB = full W fp16 (32KB); after compute, sB reused as fp32 staging for the
// accumulator fragments, then converted to fp16 g_h. 40KB static smem.
// ---------------------------------------------------------------------------
__global__ void __launch_bounds__(256) gemm_kernel(const float* __restrict__ feat) {
    __shared__ __align__(16) char smem_raw[8192 + 32768];
    __half* sA = (__half*)smem_raw;                 // [32][128]
    __half* sB = (__half*)(smem_raw + 8192);        // [128][128]
    float* stage = (float*)(smem_raw + 8192);       // [32][128] f32 (16KB, reuse)

    const int tid = threadIdx.x;
    const int base = blockIdx.x * 32;
    const int nvalid = min(32, N_NODES - base);

    // sA: convert feat rows to fp16 (pad invalid rows with 0)
    for (int i = tid; i < 32 * 32; i += 256) {
        const int r = i >> 5, c4 = i & 31;
        float4 f = (r < nvalid)
                       ? __ldg((const float4*)(feat + (size_t)(base + r) * 128) + c4)
                       : make_float4(0.f, 0.f, 0.f, 0.f);
        __half2* dp = (__half2*)(sA + r * 128 + c4 * 4);
        dp[0] = __floats2half2_rn(f.x, f.y);
        dp[1] = __floats2half2_rn(f.z, f.w);
    }
    // sB: copy g_Wh (32KB, L2-resident)
    for (int i = tid; i < 2048; i += 256)
        ((uint4*)sB)[i] = ((const uint4*)g_Wh)[i];
    __syncthreads();

    const int w = tid >> 5;
    const int m_tile = w & 1;        // 2 m-tiles of 16 nodes
    const int nb = w >> 1;           // warp covers n-tiles nb and nb+4

    wmma::fragment<wmma::accumulator, 16, 16, 16, float> c0, c1;
    wmma::fill_fragment(c0, 0.0f);
    wmma::fill_fragment(c1, 0.0f);

#pragma unroll
    for (int k = 0; k < 8; k++) {
        wmma::fragment<wmma::matrix_a, 16, 16, 16, __half, wmma::row_major> a;
        wmma::load_matrix_sync(a, sA + m_tile * 16 * 128 + k * 16, 128);
        wmma::fragment<wmma::matrix_b, 16, 16, 16, __half, wmma::row_major> b;
        wmma::load_matrix_sync(b, sB + k * 16 * 128 + nb * 16, 128);
        wmma::mma_sync(c0, a, b, c0);
        wmma::load_matrix_sync(b, sB + k * 16 * 128 + (nb + 4) * 16, 128);
        wmma::mma_sync(c1, a, b, c1);
    }
    __syncthreads();  // all warps done reading sB; reuse as fp32 staging

    wmma::store_matrix_sync(stage + m_tile * 16 * 128 + nb * 16, c0, 128,
                            wmma::mem_row_major);
    wmma::store_matrix_sync(stage + m_tile * 16 * 128 + (nb + 4) * 16, c1, 128,
                            wmma::mem_row_major);
    __syncthreads();

    // stage (fp32) -> g_h (fp16): 32*64 half2
    for (int i = tid; i < 2048; i += 256) {
        const int r = i >> 6;
        if (r < nvalid) {
            const float2 f = ((const float2*)stage)[i];
            ((__half2*)g_h)[(size_t)(base + r) * 64 + (i & 63)] =
                __floats2half2_rn(f.x, f.y);
        }
    }
}

// ---------------------------------------------------------------------------
// Kernel 2: CSR offsets via binary search (dst is sorted).
// ---------------------------------------------------------------------------
__global__ void rowptr_kernel(const int* __restrict__ dst) {
    const int n = blockIdx.x * blockDim.x + threadIdx.x;
    if (n > N_NODES) return;
    int lo = 0, hi = N_EDGES;
    while (lo < hi) {
        const int mid = (lo + hi) >> 1;
        if (__ldg(&dst[mid]) < n) lo = mid + 1;
        else hi = mid;
    }
    g_rowptr[n] = lo;
}

// ---------------------------------------------------------------------------
// Kernel 3: fused scores + softmax + aggregation. One warp per dst node,
// FOUR edges per warp iteration: 8 lanes per edge (quarter q = l>>3 picks the
// edge, ql = l&7 owns cols 16ql..16ql+15; head = ql>>1, so head-reduce is a
// single shfl_xor(1)). fp16 gathers, fp32 math in packed f32x2 (operand packs
// are allocation-free). Per-edge warp-issue count ~12 vs ~19.5 before.
// ---------------------------------------------------------------------------
__global__ void __launch_bounds__(64) attn_kernel(const int* __restrict__ src,
                                                  float* __restrict__ out) {
    const int n = (int)((blockIdx.x * 64 + threadIdx.x) >> 5);
    const int l = threadIdx.x & 31;
    if (n >= N_NODES) return;
    const int q = l >> 3;   // edge slot 0..3
    const int ql = l & 7;   // owns cols 16ql..16ql+15

    const int beg = g_rowptr[n];
    const int end = g_rowptr[n + 1];

    const uint4* __restrict__ H4 = (const uint4*)g_h;  // 16 uint4 per node

    // dst features (this lane's 16 cols), scaled by 1/sqrt(32)*log2(e)
    const float scale = 0.17677669529663689f * 1.4426950408889634f;
    ull hd[8];
    {
        const uint4 v0 = H4[(size_t)n * 16 + 2 * ql];
        const uint4 v1 = H4[(size_t)n * 16 + 2 * ql + 1];
        const unsigned int* w0 = (const unsigned int*)&v0;
        const unsigned int* w1 = (const unsigned int*)&v1;
        const ull sc2 = dup2(scale);
#pragma unroll
        for (int j = 0; j < 4; j++) hd[j] = mul2(h2f2(w0[j]), sc2);
#pragma unroll
        for (int j = 0; j < 4; j++) hd[4 + j] = mul2(h2f2(w1[j]), sc2);
    }

    ull acc[8];
#pragma unroll
    for (int j = 0; j < 8; j++) acc[j] = 0ull;
    float s = 0.f;

#pragma unroll 2
    for (int e = beg; e < end; e += 4) {
        const int idx = e + q;
        const bool valid = idx < end;
        const int sn = __ldg(&src[valid ? idx : beg]);
        const uint4 v0 = __ldg(&H4[(size_t)sn * 16 + 2 * ql]);
        const uint4 v1 = __ldg(&H4[(size_t)sn * 16 + 2 * ql + 1]);
        const unsigned int* w0 = (const unsigned int*)&v0;
        const unsigned int* w1 = (const unsigned int*)&v1;

        ull a[8];
#pragma unroll
        for (int j = 0; j < 4; j++) a[j] = h2f2(w0[j]);
#pragma unroll
        for (int j = 0; j < 4; j++) a[4 + j] = h2f2(w1[j]);

        ull d2 = 0ull;
#pragma unroll
        for (int j = 0; j < 8; j++) d2 = fma2(a[j], hd[j], d2);
        const float2 dd = unpack2(d2);
        float d = dd.x + dd.y;
        d += __shfl_xor_sync(0xffffffffu, d, 1);  // partner lane of same head

        float p = exp2f(d);
        p = valid ? p : 0.f;
        s += p;
        const ull p2 = dup2(p);
#pragma unroll
        for (int j = 0; j < 8; j++) acc[j] = fma2(p2, a[j], acc[j]);
    }

    // combine the four edge-quarters (lanes ql, ql+8, ql+16, ql+24)
#pragma unroll
    for (int off = 8; off <= 16; off <<= 1) {
#pragma unroll
        for (int j = 0; j < 8; j++) acc[j] = add2(acc[j], shfl_xor64(acc[j], off));
        s += __shfl_xor_sync(0xffffffffu, s, off);
    }

    if (q == 0) {
        const float inv = (s > 0.f) ? (1.0f / s) : 0.f;
        float4* o4 = (float4*)(out + (size_t)n * 128 + 16 * ql);
#pragma unroll
        for (int j = 0; j < 4; j++) {
            const float2 x0 = unpack2(acc[2 * j]);
            const float2 x1 = unpack2(acc[2 * j + 1]);
            float4 o;
            o.x = x0.x * inv; o.y = x0.y * inv;
            o.z = x1.x * inv; o.w = x1.y * inv;
            o4[j] = o;
        }
    }
}

// ---------------------------------------------------------------------------
extern "C" void kernel_launch(void* const* d_in, const int* in_sizes, int n_in,
                              void* d_out, int out_size) {
    const float* feat = (const float*)d_in[0];   // [N, 128] f32
    const int*   src  = (const int*)d_in[1];     // [E] i32
    const int*   dst  = (const int*)d_in[2];     // [E] i32, sorted
    const float* W    = (const float*)d_in[3];   // [128, 128] f32
    float* out = (float*)d_out;                  // [N, 128] f32

    wh_kernel<<<64, 256>>>(W);
    rowptr_kernel<<<(N_NODES + 1 + 255) / 256, 256>>>(dst);
    gemm_kernel<<<(N_NODES + 31) / 32, 256>>>(feat);
    attn_kernel<<<(N_NODES * 32 + 63) / 64, 64>>>(src, out);
}

// round 13
// speedup vs baseline: 1.1467x; 1.1467x over previous
#include <cuda_runtime.h>
#include <cuda_fp16.h>
#include <mma.h>

using namespace nvcuda;

#define N_NODES 50000
#define N_EDGES 1600000
// h layout: [N, 128] (4 heads x 32)

typedef unsigned long long ull;

// Scratch (device globals — no allocation allowed)
__device__ __half g_h[(size_t)N_NODES * 128];   // projected features fp16 [N,128]
__device__ int    g_rowptr[N_NODES + 1];        // CSR offsets over sorted dst
__device__ __half g_Wh[128 * 128];              // W in fp16, row-major [k][c]

__device__ __forceinline__ unsigned int h2_as_u32(__half2 h) {
    union { __half2 h; unsigned int u; } cvt;
    cvt.h = h;
    return cvt.u;
}

// ---------------------------------------------------------------------------
// Kernel 0: W -> fp16 (one-time, 16384 elements)
// ---------------------------------------------------------------------------
__global__ void wh_kernel(const float* __restrict__ W) {
    const int i = blockIdx.x * 256 + threadIdx.x;
    if (i < 128 * 128) g_Wh[i] = __float2half(__ldg(&W[i]));
}

// ---------------------------------------------------------------------------
// Kernel 1: h = feat @ W via wmma (HMMA fp16 in / fp32 accum / fp16 out).
// R12's version died on the per-block 32KB W->smem copy (50MB total).
// Fix: NO W staging — load_matrix_sync B fragments straight from global g_Wh
// (64KB, L1-resident, reused by all 782 blocks). 64 nodes/block, 8 warps.
// Warp w: m-tile = w>>1 (16 nodes), n-tiles (w&1)*4 .. +3 (4 frags, 32 regs).
// Output staged via smem (A smem 16KB + stage 32KB = 48KB static).
// ---------------------------------------------------------------------------
__global__ void __launch_bounds__(256) gemm_kernel(const float* __restrict__ feat) {
    __shared__ __align__(16) __half sA[64 * 128];   // 16KB
    __shared__ __align__(16) float sStage[8 * 4 * 256];  // 32KB: per-warp 4x(16x16)

    const int tid = threadIdx.x;
    const int base = blockIdx.x * 64;
    const int nvalid = min(64, N_NODES - base);

    // feat (f32) -> sA (fp16), zero-pad invalid rows
    for (int i = tid; i < 64 * 32; i += 256) {
        const int r = i >> 5, c4 = i & 31;
        float4 f = (r < nvalid)
                       ? __ldg((const float4*)(feat + (size_t)(base + r) * 128) + c4)
                       : make_float4(0.f, 0.f, 0.f, 0.f);
        __half2* dp = (__half2*)(sA + r * 128 + c4 * 4);
        dp[0] = __floats2half2_rn(f.x, f.y);
        dp[1] = __floats2half2_rn(f.z, f.w);
    }
    __syncthreads();

    const int w = tid >> 5;
    const int m_tile = w >> 1;            // 0..3
    const int n0 = (w & 1) * 4;           // n-tiles n0..n0+3

    wmma::fragment<wmma::accumulator, 16, 16, 16, float> c[4];
#pragma unroll
    for (int j = 0; j < 4; j++) wmma::fill_fragment(c[j], 0.0f);

#pragma unroll
    for (int k = 0; k < 8; k++) {
        wmma::fragment<wmma::matrix_a, 16, 16, 16, __half, wmma::row_major> a;
        wmma::load_matrix_sync(a, sA + m_tile * 16 * 128 + k * 16, 128);
#pragma unroll
        for (int j = 0; j < 4; j++) {
            wmma::fragment<wmma::matrix_b, 16, 16, 16, __half, wmma::row_major> b;
            wmma::load_matrix_sync(b, g_Wh + k * 16 * 128 + (n0 + j) * 16, 128);
            wmma::mma_sync(c[j], a, b, c[j]);
        }
    }

#pragma unroll
    for (int j = 0; j < 4; j++)
        wmma::store_matrix_sync(sStage + w * 1024 + j * 256, c[j], 16,
                                wmma::mem_row_major);
    __syncthreads();

    // sStage (f32, tiled) -> g_h (fp16, row-major). 64 nodes x 64 half2.
    for (int i = tid; i < 64 * 64; i += 256) {
        const int r = i >> 6;           // node row 0..63
        if (r >= nvalid) continue;
        const int c2 = i & 63;          // half2 col 0..63 (cols 2c2, 2c2+1)
        const int col = c2 * 2;
        const int n_tile = col >> 4;
        const int sw = (r >> 4) * 2 + (n_tile >> 2);
        const int j = n_tile & 3;
        const float2 f = *(const float2*)&sStage[sw * 1024 + j * 256 +
                                                 (r & 15) * 16 + (col & 15)];
        ((__half2*)g_h)[(size_t)(base + r) * 64 + c2] = __floats2half2_rn(f.x, f.y);
    }
}

// ---------------------------------------------------------------------------
// Kernel 2: CSR offsets via binary search (dst is sorted).
// ---------------------------------------------------------------------------
__global__ void rowptr_kernel(const int* __restrict__ dst) {
    const int n = blockIdx.x * blockDim.x + threadIdx.x;
    if (n > N_NODES) return;
    int lo = 0, hi = N_EDGES;
    while (lo < hi) {
        const int mid = (lo + hi) >> 1;
        if (__ldg(&dst[mid]) < n) lo = mid + 1;
        else hi = mid;
    }
    g_rowptr[n] = lo;
}

// ---------------------------------------------------------------------------
// Kernel 3: fused scores + softmax + aggregation — EXACT R11 version
// (measured 60.1us, regs=32, occ=84%, issue=76.6%; the R12 8-lane rewrite
// regressed via register pressure). One warp per dst node, 64-thread blocks.
// ---------------------------------------------------------------------------
__global__ void __launch_bounds__(64) attn_kernel(const int* __restrict__ src,
                                                  float* __restrict__ out) {
    const int n = (int)((blockIdx.x * blockDim.x + threadIdx.x) >> 5);
    const int l = threadIdx.x & 31;
    if (n >= N_NODES) return;

    const int beg = g_rowptr[n];
    const int end = g_rowptr[n + 1];

    const uint2* __restrict__ H2 = (const uint2*)g_h;

    // 1/sqrt(32) * log2(e): fold softmax scale + exp2 conversion into hd
    const float scale_d = 0.17677669529663689f * 1.4426950408889634f;
    float2 hd0, hd1;
    {
        const uint2 v = H2[n * 32 + l];
        const float2 a = __half22float2(*(const half2*)&v.x);
        const float2 b = __half22float2(*(const half2*)&v.y);
        hd0.x = a.x * scale_d; hd0.y = a.y * scale_d;
        hd1.x = b.x * scale_d; hd1.y = b.y * scale_d;
    }

    float s = 0.f;
    float2 acc0 = make_float2(0.f, 0.f);
    float2 acc1 = make_float2(0.f, 0.f);

    int e = beg;
    for (; e + 4 <= end; e += 4) {
        int sn[4];
#pragma unroll
        for (int j = 0; j < 4; j++) sn[j] = __ldg(&src[e + j]);
        uint2 v[4];
#pragma unroll
        for (int j = 0; j < 4; j++) v[j] = __ldg(&H2[sn[j] * 32 + l]);
#pragma unroll
        for (int j = 0; j < 4; j++) {
            const float2 a = __half22float2(*(const half2*)&v[j].x);
            const float2 b = __half22float2(*(const half2*)&v[j].y);
            float d = a.x * hd0.x;
            d = fmaf(a.y, hd0.y, d);
            d = fmaf(b.x, hd1.x, d);
            d = fmaf(b.y, hd1.y, d);
            d += __shfl_xor_sync(0xffffffffu, d, 1);
            d += __shfl_xor_sync(0xffffffffu, d, 2);
            d += __shfl_xor_sync(0xffffffffu, d, 4);
            const float p = exp2f(d);   // single MUFU.EX2
            s += p;
            acc0.x = fmaf(p, a.x, acc0.x);
            acc0.y = fmaf(p, a.y, acc0.y);
            acc1.x = fmaf(p, b.x, acc1.x);
            acc1.y = fmaf(p, b.y, acc1.y);
        }
    }
    for (; e < end; e++) {
        const int sn = __ldg(&src[e]);
        const uint2 v = __ldg(&H2[sn * 32 + l]);
        const float2 a = __half22float2(*(const half2*)&v.x);
        const float2 b = __half22float2(*(const half2*)&v.y);
        float d = a.x * hd0.x;
        d = fmaf(a.y, hd0.y, d);
        d = fmaf(b.x, hd1.x, d);
        d = fmaf(b.y, hd1.y, d);
        d += __shfl_xor_sync(0xffffffffu, d, 1);
        d += __shfl_xor_sync(0xffffffffu, d, 2);
        d += __shfl_xor_sync(0xffffffffu, d, 4);
        const float p = exp2f(d);
        s += p;
        acc0.x = fmaf(p, a.x, acc0.x);
        acc0.y = fmaf(p, a.y, acc0.y);
        acc1.x = fmaf(p, b.x, acc1.x);
        acc1.y = fmaf(p, b.y, acc1.y);
    }

    const float inv = (s > 0.f) ? (1.0f / s) : 0.f;
    float4 o;
    o.x = acc0.x * inv; o.y = acc0.y * inv;
    o.z = acc1.x * inv; o.w = acc1.y * inv;
    ((float4*)out)[n * 32 + l] = o;
}

// ---------------------------------------------------------------------------
extern "C" void kernel_launch(void* const* d_in, const int* in_sizes, int n_in,
                              void* d_out, int out_size) {
    const float* feat = (const float*)d_in[0];   // [N, 128] f32
    const int*   src  = (const int*)d_in[1];     // [E] i32
    const int*   dst  = (const int*)d_in[2];     // [E] i32, sorted
    const float* W    = (const float*)d_in[3];   // [128, 128] f32
    float* out = (float*)d_out;                  // [N, 128] f32

    wh_kernel<<<64, 256>>>(W);
    rowptr_kernel<<<(N_NODES + 1 + 255) / 256, 256>>>(dst);
    gemm_kernel<<<(N_NODES + 63) / 64, 256>>>(feat);
    attn_kernel<<<(N_NODES * 32 + 63) / 64, 64>>>(src, out);
}

// round 15
// speedup vs baseline: 1.4717x; 1.2835x over previous
#include <cuda_runtime.h>
#include <cuda_fp16.h>
#include <mma.h>

using namespace nvcuda;

#define N_NODES 50000
#define N_EDGES 1600000
#define GEMM_GRID 444
#define N_TILES 3125          // 50000 / 16

typedef unsigned long long ull;

// Scratch (device globals — no allocation allowed)
__device__ __align__(16) __half g_h[(size_t)N_NODES * 128];  // projected fp16 [N,128]
__device__ int    g_rowptr[N_NODES + 1];                     // CSR offsets (dst sorted)
__device__ __align__(16) __half g_Wh[128 * 128];             // W fp16 row-major [k][c]

// ---------------------------------------------------------------------------
// Packed f32x2 helpers (packs/unpacks of distinct values are allocation-only)
// ---------------------------------------------------------------------------
__device__ __forceinline__ ull fma2(ull a, ull b, ull c) {
    ull d;
    asm("fma.rn.f32x2 %0, %1, %2, %3;" : "=l"(d) : "l"(a), "l"(b), "l"(c));
    return d;
}
__device__ __forceinline__ ull mul2(ull a, ull b) {
    ull d;
    asm("mul.rn.f32x2 %0, %1, %2;" : "=l"(d) : "l"(a), "l"(b));
    return d;
}
__device__ __forceinline__ ull dup2(float x) {
    ull r;
    asm("mov.b64 %0, {%1, %1};" : "=l"(r) : "f"(x));
    return r;
}
__device__ __forceinline__ float2 unpack2(ull u) {
    float2 f;
    asm("mov.b64 {%0, %1}, %2;" : "=f"(f.x), "=f"(f.y) : "l"(u));
    return f;
}
// half2 (as u32) -> packed f32x2 (2 cvt, packs free)
__device__ __forceinline__ ull h2f2(unsigned int h) {
    ull r;
    asm("{\n\t"
        ".reg .b16 lo, hi;\n\t"
        ".reg .f32 f0, f1;\n\t"
        "mov.b32 {lo, hi}, %1;\n\t"
        "cvt.f32.f16 f0, lo;\n\t"
        "cvt.f32.f16 f1, hi;\n\t"
        "mov.b64 %0, {f0, f1};\n\t"
        "}" : "=l"(r) : "r"(h));
    return r;
}
__device__ __forceinline__ ull shfl_xor64(ull v, int m) {
    unsigned lo = (unsigned)v, hi = (unsigned)(v >> 32);
    lo = __shfl_xor_sync(0xffffffffu, lo, m);
    hi = __shfl_xor_sync(0xffffffffu, hi, m);
    return ((ull)hi << 32) | (ull)lo;
}
__device__ __forceinline__ unsigned int h2_as_u32(__half2 h) {
    union { __half2 h; unsigned int u; } cvt;
    cvt.h = h;
    return cvt.u;
}

// ---------------------------------------------------------------------------
// Kernel 0: W -> fp16 (one-time)
// ---------------------------------------------------------------------------
__global__ void wh_kernel(const float* __restrict__ W) {
    const int i = blockIdx.x * 256 + threadIdx.x;
    if (i < 128 * 128) g_Wh[i] = __float2half(__ldg(&W[i]));
}

// ---------------------------------------------------------------------------
// Kernel 1: h = feat @ W via wmma — persistent blocks, B-frags in registers.
// Warp w owns output cols 16w..16w+15; loads its 8 B fragments (all of K)
// ONCE per block, then streams 16-node A tiles. A smem padded to ldm=136
// (row stride 272B = 4-bank shift -> conflict-free ldmatrix; 128 would be
// 8-way conflicted). Per tile: 8 ldsm + 8 HMMA + warp-private epilogue.
// R13's ~48us came from per-tile B fragment reloads from global; this does
// 8 B-frag loads per block TOTAL.
// ---------------------------------------------------------------------------
__global__ void __launch_bounds__(256) gemm_kernel(const float* __restrict__ feat) {
    __shared__ __align__(16) __half sA[16 * 136];     // 4.25KB, padded
    __shared__ __align__(16) float sStage[8 * 256];   // 8KB, 1KB per warp

    const int tid = threadIdx.x;
    const int w = tid >> 5;
    const int l = tid & 31;

    // B fragments: one-time per block (cols w*16..w*16+15, all 8 k-steps)
    wmma::fragment<wmma::matrix_b, 16, 16, 16, __half, wmma::row_major> B[8];
#pragma unroll
    for (int k = 0; k < 8; k++)
        wmma::load_matrix_sync(B[k], g_Wh + k * 16 * 128 + w * 16, 128);

    for (int t = blockIdx.x; t < N_TILES; t += GEMM_GRID) {
        const int base = t * 16;

        __syncthreads();  // previous tile's ldsm reads complete
        // A tile: 16 rows x 128 f32 = 512 float4, convert to fp16, padded STS
        for (int i = tid; i < 512; i += 256) {
            const int r = i >> 5, c4 = i & 31;
            const float4 f = __ldg((const float4*)(feat + (size_t)(base + r) * 128) + c4);
            unsigned int* dp = (unsigned int*)sA + r * 68 + c4 * 2;
            dp[0] = h2_as_u32(__floats2half2_rn(f.x, f.y));
            dp[1] = h2_as_u32(__floats2half2_rn(f.z, f.w));
        }
        __syncthreads();

        wmma::fragment<wmma::accumulator, 16, 16, 16, float> c;
        wmma::fill_fragment(c, 0.0f);
#pragma unroll
        for (int k = 0; k < 8; k++) {
            wmma::fragment<wmma::matrix_a, 16, 16, 16, __half, wmma::row_major> a;
            wmma::load_matrix_sync(a, sA + k * 16, 136);
            wmma::mma_sync(c, a, B[k], c);
        }

        // warp-private epilogue: frag -> smem -> fp16 g_h (no block sync)
        wmma::store_matrix_sync(sStage + w * 256, c, 16, wmma::mem_row_major);
        __syncwarp();
        {
            const int r = l >> 1, c0 = (l & 1) * 8;
            const float* sp = sStage + w * 256 + r * 16 + c0;
            uint4 o;
            o.x = h2_as_u32(__floats2half2_rn(sp[0], sp[1]));
            o.y = h2_as_u32(__floats2half2_rn(sp[2], sp[3]));
            o.z = h2_as_u32(__floats2half2_rn(sp[4], sp[5]));
            o.w = h2_as_u32(__floats2half2_rn(sp[6], sp[7]));
            *(uint4*)(g_h + (size_t)(base + r) * 128 + w * 16 + c0) = o;
        }
        __syncwarp();  // stage reads done before next tile's store
    }
}

// ---------------------------------------------------------------------------
// Kernel 2: CSR offsets via binary search (dst is sorted).
// ---------------------------------------------------------------------------
__global__ void rowptr_kernel(const int* __restrict__ dst) {
    const int n = blockIdx.x * blockDim.x + threadIdx.x;
    if (n > N_NODES) return;
    int lo = 0, hi = N_EDGES;
    while (lo < hi) {
        const int mid = (lo + hi) >> 1;
        if (__ldg(&dst[mid]) < n) lo = mid + 1;
        else hi = mid;
    }
    g_rowptr[n] = lo;
}

// ---------------------------------------------------------------------------
// Kernel 3: fused scores + softmax + aggregation. One warp per dst node,
// TWO edges per iteration: 16 lanes per edge (half = l>>4), lane owns 8 cols
// = one uint4 gather (0.5 LDG/edge). head = (l&15)>>2; head-reduce = 2 shfls.
// fp32 math in packed f32x2. ~45 regs (R12's 8-lane variant needed 72 and
// lost occupancy; this keeps the occupancy AND cuts issues/edge ~25 -> ~17).
// ---------------------------------------------------------------------------
__global__ void __launch_bounds__(64) attn_kernel(const int* __restrict__ src,
                                                  float* __restrict__ out) {
    const int n = (int)((blockIdx.x * 64 + threadIdx.x) >> 5);
    const int l = threadIdx.x & 31;
    if (n >= N_NODES) return;
    const int half = l >> 4;   // edge slot 0/1
    const int hl = l & 15;     // owns cols 8*hl .. 8*hl+7

    const int beg = g_rowptr[n];
    const int end = g_rowptr[n + 1];

    const uint4* __restrict__ H4 = (const uint4*)g_h;  // 16 uint4 per node row

    // dst features (lane's 8 cols), scaled by 1/sqrt(32)*log2(e)
    const float scale = 0.17677669529663689f * 1.4426950408889634f;
    ull hd[4];
    {
        const uint4 v = H4[(size_t)n * 16 + hl];
        const unsigned int* vw = (const unsigned int*)&v;
        const ull sc2 = dup2(scale);
#pragma unroll
        for (int j = 0; j < 4; j++) hd[j] = mul2(h2f2(vw[j]), sc2);
    }

    ull acc[4] = {0ull, 0ull, 0ull, 0ull};
    float s = 0.f;

#pragma unroll 2
    for (int e = beg; e < end; e += 2) {
        const int idx = e + half;
        const bool valid = idx < end;
        const int sn = __ldg(&src[valid ? idx : beg]);
        const uint4 v = __ldg(&H4[(size_t)sn * 16 + hl]);
        const unsigned int* vw = (const unsigned int*)&v;

        ull a[4];
#pragma unroll
        for (int j = 0; j < 4; j++) a[j] = h2f2(vw[j]);

        ull d2 = 0ull;
#pragma unroll
        for (int j = 0; j < 4; j++) d2 = fma2(a[j], hd[j], d2);
        const float2 dd = unpack2(d2);
        float d = dd.x + dd.y;
        // reduce over the 4 lanes of this head (hl&3) — stays within half
        d += __shfl_xor_sync(0xffffffffu, d, 1);
        d += __shfl_xor_sync(0xffffffffu, d, 2);

        float p = exp2f(d);
        p = valid ? p : 0.f;
        s += p;
        const ull p2 = dup2(p);
#pragma unroll
        for (int j = 0; j < 4; j++) acc[j] = fma2(p2, a[j], acc[j]);
    }

    // combine the two edge-halves
    s += __shfl_xor_sync(0xffffffffu, s, 16);
#pragma unroll
    for (int j = 0; j < 4; j++) acc[j] = fma2(dup2(1.f), shfl_xor64(acc[j], 16), acc[j]);

    if (half == 0) {
        const float inv = (s > 0.f) ? (1.0f / s) : 0.f;
        float* op = out + (size_t)n * 128 + 8 * hl;
        const float2 x0 = unpack2(acc[0]);
        const float2 x1 = unpack2(acc[1]);
        const float2 x2 = unpack2(acc[2]);
        const float2 x3 = unpack2(acc[3]);
        float4 o0, o1;
        o0.x = x0.x * inv; o0.y = x0.y * inv; o0.z = x1.x * inv; o0.w = x1.y * inv;
        o1.x = x2.x * inv; o1.y = x2.y * inv; o1.z = x3.x * inv; o1.w = x3.y * inv;
        ((float4*)op)[0] = o0;
        ((float4*)op)[1] = o1;
    }
}

// ---------------------------------------------------------------------------
extern "C" void kernel_launch(void* const* d_in, const int* in_sizes, int n_in,
                              void* d_out, int out_size) {
    const float* feat = (const float*)d_in[0];   // [N, 128] f32
    const int*   src  = (const int*)d_in[1];     // [E] i32
    const int*   dst  = (const int*)d_in[2];     // [E] i32, sorted
    const float* W    = (const float*)d_in[3];   // [128, 128] f32
    float* out = (float*)d_out;                  // [N, 128] f32

    wh_kernel<<<64, 256>>>(W);
    rowptr_kernel<<<(N_NODES + 1 + 255) / 256, 256>>>(dst);
    gemm_kernel<<<GEMM_GRID, 256>>>(feat);
    attn_kernel<<<(N_NODES * 32 + 63) / 64, 64>>>(src, out);
}